// round 15
// baseline (speedup 1.0000x reference)
#include <cuda_runtime.h>
#include <cuda_bf16.h>
#include <math.h>
#include <stddef.h>

typedef unsigned long long ull;
typedef unsigned int uint;

// ---------------------------------------------------------------------------
// SPINN TreeLSTM: level-scheduled tree evaluation.
//   Big levels (M>128): mma.sync bf16x3, ldmatrix, 3-stage cp.async pipeline,
//                       A gathered from persistent bf16 node cache (no per-level
//                       conversion pass). 256 threads, warp tile 32x64.
//   Mid levels (33..128): FFMA2 split-K, 128-node tile.
//   Tiny levels (<=32):   FFMA2 split-K, 32-node tile.
// scan_kernel stays launch #4 (ncu capture slot).
// R15: identical to R14 (container-level infra failure; code re-audited clean).
// ---------------------------------------------------------------------------

#define BB 128
#define LL 128
#define EE 512
#define HH 512
#define TT 255
#define NN 127
#define TWO_H 1024
#define FIVE_H 2560
#define NLE (BB*LL)
#define PS 8

// dynamic smem: 3 chunk buffers of 40960B: [AH 10240 | AL 10240 | BH 10240 | BL 10240]
#define GBUF   40960
#define A_LO   10240
#define B_HI   20480
#define B_LO   30720
#define CTRL_OFF 122880
#define SMEM_SZ  131072

struct Ctrl {
    const float* hl[128];
    const float* hr[128];
    int  idx[128];
};

// ------------------------- scratch (static device memory) ------------------
__device__ float g_tmp[NLE * TWO_H];
__device__ float g_hbuf[BB * LL * HH];
__device__ float g_cbuf[BB * LL * HH];
__device__ float g_node_h[BB * NN * HH];
__device__ float g_node_c[BB * NN * HH];
__device__ float g_gates[8192 * FIVE_H];           // tensor-path gate preacts (+split slab)
__device__ float g_part[128 * FIVE_H * PS];        // small-path split-K partials
__device__ __nv_bfloat16 g_wb_hi[FIVE_H * TWO_H];  // W bf16 hi, [n][k]
__device__ __nv_bfloat16 g_wb_lo[FIVE_H * TWO_H];  // W bf16 lo, [n][k]
__device__ __nv_bfloat16 g_nb_hi[(size_t)BB * 256 * HH]; // per-node h bf16 hi
__device__ __nv_bfloat16 g_nb_lo[(size_t)BB * 256 * HH]; // per-node h bf16 lo
__device__ float g_sum[TWO_H];
__device__ float g_sumsq[TWO_H];
__device__ int2  g_ch[BB * NN];
__device__ int   g_items[BB * NN];
__device__ int   g_lv_start[132];
__device__ int   g_maxlvl;
__device__ int   g_fin[BB];
__device__ int            g_bar_count;
__device__ volatile int   g_bar_gen;

__device__ __forceinline__ float sigf(float x) { return 1.0f / (1.0f + expf(-x)); }

__device__ __forceinline__ ull ffma2(ull x, ull w, ull a) {
    asm("fma.rn.f32x2 %0, %1, %2, %0;" : "+l"(a) : "l"(x), "l"(w));
    return a;
}
__device__ __forceinline__ ull pk2(float v) {
    ull r; asm("mov.b64 %0, {%1, %2};" : "=l"(r) : "f"(v), "f"(v)); return r;
}
__device__ __forceinline__ float2 upk(ull v) {
    float2 f; asm("mov.b64 {%0, %1}, %2;" : "=f"(f.x), "=f"(f.y) : "l"(v)); return f;
}
__device__ __forceinline__ uint s2u(const void* p) {
    uint a; asm("{ .reg .u64 t; cvta.to.shared.u64 t, %1; cvt.u32.u64 %0, t; }"
                : "=r"(a) : "l"(p));
    return a;
}

// cp.async 16B global->shared
__device__ __forceinline__ void cp16(uint dst, const void* src) {
    asm volatile("cp.async.cg.shared.global [%0], [%1], 16;" :: "r"(dst), "l"(src));
}
__device__ __forceinline__ void cp_commit() {
    asm volatile("cp.async.commit_group;" ::: "memory");
}
template <int N>
__device__ __forceinline__ void cp_wait() {
    asm volatile("cp.async.wait_group %0;" :: "n"(N) : "memory");
}

// mma.sync m16n8k16 row.col f32.bf16.bf16.f32
__device__ __forceinline__ void mma_bf16(float* c, uint a0, uint a1, uint a2, uint a3,
                                         uint b0, uint b1) {
    asm volatile("mma.sync.aligned.m16n8k16.row.col.f32.bf16.bf16.f32 "
                 "{%0,%1,%2,%3}, {%4,%5,%6,%7}, {%8,%9}, {%0,%1,%2,%3};"
                 : "+f"(c[0]), "+f"(c[1]), "+f"(c[2]), "+f"(c[3])
                 : "r"(a0), "r"(a1), "r"(a2), "r"(a3), "r"(b0), "r"(b1));
}

#define LDSM4(r0, r1, r2, r3, addr) asm volatile( \
    "ldmatrix.sync.aligned.m8n8.x4.shared.b16 {%0,%1,%2,%3}, [%4];" \
    : "=r"(r0), "=r"(r1), "=r"(r2), "=r"(r3) : "r"(addr))

__device__ __forceinline__ const float* hsrc(int b, int id) {
    return (id < 128) ? (g_hbuf + (b * LL + id) * HH)
                      : (g_node_h + (b * NN + (id - 128)) * HH);
}
__device__ __forceinline__ const float* csrc(int b, int id) {
    return (id < 128) ? (g_cbuf + (b * LL + id) * HH)
                      : (g_node_c + (b * NN + (id - 128)) * HH);
}
__device__ __forceinline__ void store_nb(int b, int nid, int j, float h) {
    __nv_bfloat16 hb = __float2bfloat16(h);
    size_t o = ((size_t)b * 256 + nid) * HH + j;
    g_nb_hi[o] = hb;
    g_nb_lo[o] = __float2bfloat16(h - __bfloat162float(hb));
}

__device__ __forceinline__ void grid_barrier(int nblk) {
    __syncthreads();
    if (threadIdx.x == 0) {
        __threadfence();
        int gen = g_bar_gen;
        if (atomicAdd(&g_bar_count, 1) == nblk - 1) {
            g_bar_count = 0;
            __threadfence();
            g_bar_gen = gen + 1;
        } else {
            while (g_bar_gen == gen) { __nanosleep(32); }
        }
        __threadfence();
    }
    __syncthreads();
}

// ------------------- launch #1: word GEMM (f32x2) + stat zeroing ------------
__global__ __launch_bounds__(256) void word_gemm(
    const float* __restrict__ A, const float* __restrict__ Wm,
    const float* __restrict__ bias)
{
    __shared__ float As[32 * 129];
    __shared__ __align__(16) float Bs[32][64];
    const int tid = threadIdx.x;
    const int tx = tid & 15;
    const int ty = tid >> 4;
    const int rowBase = blockIdx.y * 128;
    const int colBase = blockIdx.x * 64;

    if (blockIdx.x == 0 && blockIdx.y == 0) {
        for (int i = tid; i < TWO_H; i += 256) { g_sum[i] = 0.f; g_sumsq[i] = 0.f; }
    }

    ull acc[8][2];
#pragma unroll
    for (int i = 0; i < 8; i++) { acc[i][0] = 0ull; acc[i][1] = 0ull; }

    for (int k0 = 0; k0 < EE; k0 += 32) {
#pragma unroll
        for (int i = 0; i < 4; i++) {
            int f = tid + i * 256;
            int r = f >> 3, c4 = f & 7;
            float4 v = *(const float4*)(A + (rowBase + r) * EE + k0 + c4 * 4);
            As[(c4 * 4 + 0) * 129 + r] = v.x;
            As[(c4 * 4 + 1) * 129 + r] = v.y;
            As[(c4 * 4 + 2) * 129 + r] = v.z;
            As[(c4 * 4 + 3) * 129 + r] = v.w;
        }
#pragma unroll
        for (int i = 0; i < 2; i++) {
            int f = tid + i * 256;
            int r = f >> 4, c4 = f & 15;
            *(float4*)&Bs[r][c4 * 4] =
                *(const float4*)(Wm + (k0 + r) * TWO_H + colBase + c4 * 4);
        }
        __syncthreads();
#pragma unroll 8
        for (int kk = 0; kk < 32; kk++) {
            const float* ar = As + kk * 129 + ty * 8;
            ulonglong2 w2 = *(const ulonglong2*)&Bs[kk][tx * 4];
#pragma unroll
            for (int i = 0; i < 8; i++) {
                ull xp = pk2(ar[i]);
                acc[i][0] = ffma2(xp, w2.x, acc[i][0]);
                acc[i][1] = ffma2(xp, w2.y, acc[i][1]);
            }
        }
        __syncthreads();
    }

    const int col = colBase + tx * 4;
    float2 b0 = *(const float2*)(bias + col);
    float2 b1 = *(const float2*)(bias + col + 2);
#pragma unroll
    for (int i = 0; i < 8; i++) {
        int row = rowBase + ty * 8 + i;
        float2 v0 = upk(acc[i][0]);
        float2 v1 = upk(acc[i][1]);
        v0.x += b0.x; v0.y += b0.y;
        v1.x += b1.x; v1.y += b1.y;
        *(float2*)&g_tmp[row * TWO_H + col] = v0;
        *(float2*)&g_tmp[row * TWO_H + col + 2] = v1;
    }
}

// ----- launch #2: fused bn_stats + wprep + meta tree build ------------------
__global__ __launch_bounds__(256) void stats_wprep_meta(
    const float* __restrict__ W, const int* __restrict__ trans)
{
    __shared__ int cnt[132];
    __shared__ int cur[132];
    __shared__ int smax;
    const int bx = blockIdx.x;
    const int tid = threadIdx.x;

    if (bx < 1024) {
        int ch = (bx & 3) * 256 + tid;
        int rowBase = (bx >> 2) * 64;
        float s = 0.f, q = 0.f;
#pragma unroll 4
        for (int r = 0; r < 64; r++) {
            float v = g_tmp[(rowBase + r) * TWO_H + ch];
            s += v; q += v * v;
        }
        atomicAdd(&g_sum[ch], s);
        atomicAdd(&g_sumsq[ch], q);
    } else if (bx < 11264) {
        int f = (bx - 1024) * 256 + tid;       // f = k*2560 + n
        if (f < TWO_H * FIVE_H) {
            int k = f / FIVE_H, n = f - k * FIVE_H;
            float w = W[f];
            __nv_bfloat16 hb = __float2bfloat16(w);
            float rest = w - __bfloat162float(hb);
            __nv_bfloat16 lb = __float2bfloat16(rest);
            g_wb_hi[n * TWO_H + k] = hb;
            g_wb_lo[n * TWO_H + k] = lb;
        }
    } else {
        int b = tid;
        for (int i = b; i < 132; i += 256) cnt[i] = 0;
        if (b == 0) smax = 0;
        __syncthreads();
        if (b < 128) {
            int sid[130];
            int slv[130];
            int nlv[NN];
            int ptr = 0, bp = 0, n = 0;
            for (int t = 0; t < TT; t++) {
                int act = trans[b * TT + t];
                if (act == 2) {
                    sid[ptr] = bp; slv[ptr] = 0; ptr++; bp++;
                } else if (act == 3) {
                    int lv = max(slv[ptr - 2], slv[ptr - 1]) + 1;
                    g_ch[b * NN + n] = make_int2(sid[ptr - 2], sid[ptr - 1]);
                    nlv[n] = lv;
                    sid[ptr - 2] = 128 + n; slv[ptr - 2] = lv;
                    ptr--; n++;
                }
            }
            g_fin[b] = sid[0];
            int mymax = 0;
            for (int i = 0; i < n; i++) {
                atomicAdd(&cnt[nlv[i]], 1);
                mymax = max(mymax, nlv[i]);
            }
            atomicMax(&smax, mymax);
            __syncthreads();
            if (b == 0) {
                int a = 0;
                for (int lv = 0; lv <= 130; lv++) {
                    cur[lv] = a;
                    g_lv_start[lv] = a;
                    a += cnt[lv];
                }
                g_lv_start[131] = a;
                g_maxlvl = smax;
            }
            __syncthreads();
            for (int i = 0; i < n; i++) {
                int idx = atomicAdd(&cur[nlv[i]], 1);
                g_items[idx] = (b << 7) | i;
            }
        } else {
            __syncthreads();
            __syncthreads();
        }
    }
}

// ------- launch #3: bn apply + finalize + leaf bf16 cache fill --------------
__global__ __launch_bounds__(256) void bn_apply_fin(
    const float* __restrict__ gamma, const float* __restrict__ beta)
{
    int id = blockIdx.x * 256 + threadIdx.x;       // < 1024*1024
    int ch = id & 1023;
    int rb2 = id >> 10;
    const float invN = 1.0f / (float)NLE;
    float mean = g_sum[ch] * invN;
    float var  = g_sumsq[ch] * invN - mean * mean;
    float sc   = gamma[ch] * rsqrtf(var + 1e-5f);
    float sh   = beta[ch] - mean * sc;
#pragma unroll 4
    for (int rr = 0; rr < 16; rr++) {
        int row = rb2 * 16 + rr;
        float v = g_tmp[row * TWO_H + ch] * sc + sh;
        if (ch < HH) {
            g_hbuf[row * HH + ch] = v;
            store_nb(row >> 7, row & 127, ch, v);   // leaf bf16 cache
        } else {
            g_cbuf[row * HH + (ch - HH)] = v;
        }
    }
}

// ------------------- launch #4: persistent level-scan kernel ----------------
extern __shared__ char dsm_raw[];

__global__ __launch_bounds__(256) void scan_kernel(
    const float* __restrict__ W, const float* __restrict__ rb, int nblk)
{
    const int tid = threadIdx.x;
    const int lane = tid & 31;
    const int wid = tid >> 5;
    const int wm = wid >> 1;           // 0..3 : warp m-block (32 rows)
    const int wn = wid & 1;            // 0..1 : warp n-block (64 cols)
    const int g = lane >> 2;
    const int tig = lane & 3;

    char* base = dsm_raw;
    Ctrl* C = (Ctrl*)(base + CTRL_OFF);
    float* Xs = (float*)(base);            // small paths (aliases buffers)
    float* Ws = (float*)(base + 16896);
    const uint s0 = s2u(base);
    const ptrdiff_t ndel = (const char*)g_nb_lo - (const char*)g_nb_hi;

    // ldmatrix per-thread address bases
    const int jmat = lane >> 3, jr = lane & 7;
    uint aBase[2], bBase[4];
    {
#pragma unroll
        for (int mf = 0; mf < 2; mf++)
            aBase[mf] = s0 + (uint)((wm * 32 + mf * 16 + (jmat & 1) * 8 + jr) * 80
                                    + (jmat >> 1) * 16);
#pragma unroll
        for (int p = 0; p < 4; p++)
            bBase[p] = s0 + B_HI + (uint)((wn * 64 + (2 * p + (jmat >> 1)) * 8 + jr) * 80
                                          + (jmat & 1) * 16);
    }

    const int r2 = tid >> 1, hf = tid & 1;       // cp.async staging coords
    const uint dst_d = (uint)(r2 * 80 + hf * 32);
    const int maxlvl = g_maxlvl;

    for (int lv = 1; lv <= maxlvl; lv++) {
        const int start = g_lv_start[lv];
        const int M = g_lv_start[lv + 1] - start;
        if (M <= 0) { grid_barrier(nblk); continue; }

        if (M > 128) {
            // ========= mma path: A gathered from bf16 node cache ============
            const int mtiles = (M + 127) >> 7;
            const int tiles0 = mtiles * 20;
            int ks = 1;
            if (tiles0 * 2 <= nblk) ks = 2;
            const int cpu2 = 32 / ks;
            const int units = tiles0 * ks;

            for (int u = blockIdx.x; u < units; u += nblk) {
                const int t2 = u % tiles0;
                const int sp = u / tiles0;
                const int mt = t2 / 20;
                const int nt = t2 - mt * 20;
                const int c0 = sp * cpu2, c1 = c0 + cpu2;

                if (tid < 128) {
                    int gi = start + mt * 128 + tid;
                    bool valid = gi < start + M;
                    int item = g_items[valid ? gi : start];
                    int b = item >> 7, n = item & 127;
                    int2 ch = g_ch[b * NN + n];
                    C->hl[tid] = (const float*)(g_nb_hi + ((size_t)b * 256 + ch.x) * HH);
                    C->hr[tid] = (const float*)(g_nb_hi + ((size_t)b * 256 + ch.y) * HH);
                }
                __syncthreads();

                const __nv_bfloat16* sl = (const __nv_bfloat16*)C->hl[r2];
                const __nv_bfloat16* sr = (const __nv_bfloat16*)C->hr[r2];
                const __nv_bfloat16* sbH = g_wb_hi + (size_t)(nt * 128 + r2) * TWO_H;
                const __nv_bfloat16* sbL = g_wb_lo + (size_t)(nt * 128 + r2) * TWO_H;

                // issue first 3 stages
#pragma unroll
                for (int st = 0; st < 3; st++) {
                    int chk = c0 + st;
                    uint db = s0 + (uint)st * GBUF + dst_d;
                    const __nv_bfloat16* sa = (chk < 16 ? sl : sr)
                                              + ((chk & 15) * 32 + hf * 16);
                    int ko = chk * 32 + hf * 16;
                    cp16(db,              sa);
                    cp16(db + 16,         sa + 8);
                    cp16(db + A_LO,       (const char*)sa + ndel);
                    cp16(db + A_LO + 16,  (const char*)(sa + 8) + ndel);
                    cp16(db + B_HI,       sbH + ko);
                    cp16(db + B_HI + 16,  sbH + ko + 8);
                    cp16(db + B_LO,       sbL + ko);
                    cp16(db + B_LO + 16,  sbL + ko + 8);
                    cp_commit();
                }

                float acc[2][8][4];
#pragma unroll
                for (int mf = 0; mf < 2; mf++)
#pragma unroll
                    for (int nf = 0; nf < 8; nf++)
#pragma unroll
                        for (int q = 0; q < 4; q++) acc[mf][nf][q] = 0.f;

                int bufi = 0;
                for (int chk = c0; chk < c1; chk++) {
                    if (chk + 2 < c1)      cp_wait<2>();
                    else if (chk + 1 < c1) cp_wait<1>();
                    else                   cp_wait<0>();
                    __syncthreads();

                    const uint bufo = (uint)bufi * GBUF;
#pragma unroll
                    for (int half = 0; half < 2; half++) {
                        const uint kb = bufo + (uint)half * 32;
                        uint bh[8][2], bl[8][2];
#pragma unroll
                        for (int p = 0; p < 4; p++) {
                            LDSM4(bh[2 * p][0], bh[2 * p][1],
                                  bh[2 * p + 1][0], bh[2 * p + 1][1], bBase[p] + kb);
                            LDSM4(bl[2 * p][0], bl[2 * p][1],
                                  bl[2 * p + 1][0], bl[2 * p + 1][1],
                                  bBase[p] + kb + (B_LO - B_HI));
                        }
#pragma unroll
                        for (int mf = 0; mf < 2; mf++) {
                            uint a0, a1, a2, a3, l0, l1, l2, l3;
                            LDSM4(a0, a1, a2, a3, aBase[mf] + kb);
                            LDSM4(l0, l1, l2, l3, aBase[mf] + kb + A_LO);
#pragma unroll
                            for (int nf = 0; nf < 8; nf++) {
                                mma_bf16(acc[mf][nf], a0, a1, a2, a3, bh[nf][0], bh[nf][1]);
                                mma_bf16(acc[mf][nf], l0, l1, l2, l3, bh[nf][0], bh[nf][1]);
                                mma_bf16(acc[mf][nf], a0, a1, a2, a3, bl[nf][0], bl[nf][1]);
                            }
                        }
                    }
                    __syncthreads();

                    if (chk + 3 < c1) {
                        int nchk = chk + 3;
                        uint db = s0 + (uint)bufi * GBUF + dst_d;
                        const __nv_bfloat16* sa = (nchk < 16 ? sl : sr)
                                                  + ((nchk & 15) * 32 + hf * 16);
                        int ko = nchk * 32 + hf * 16;
                        cp16(db,              sa);
                        cp16(db + 16,         sa + 8);
                        cp16(db + A_LO,       (const char*)sa + ndel);
                        cp16(db + A_LO + 16,  (const char*)(sa + 8) + ndel);
                        cp16(db + B_HI,       sbH + ko);
                        cp16(db + B_HI + 16,  sbH + ko + 8);
                        cp16(db + B_LO,       sbL + ko);
                        cp16(db + B_LO + 16,  sbL + ko + 8);
                        cp_commit();
                    }
                    bufi = (bufi == 2) ? 0 : bufi + 1;
                }

                // write accumulators (split slab sp*2048 rows)
#pragma unroll
                for (int mf = 0; mf < 2; mf++) {
                    int row = wm * 32 + mf * 16 + g;
                    int gi = sp * 2048 + mt * 128 + row;
                    float* dst0 = g_gates + (size_t)gi * FIVE_H;
#pragma unroll
                    for (int nf = 0; nf < 8; nf++) {
                        int col = nt * 128 + wn * 64 + nf * 8 + 2 * tig;
                        *(float2*)(dst0 + col) =
                            make_float2(acc[mf][nf][0], acc[mf][nf][1]);
                        *(float2*)(dst0 + 8 * FIVE_H + col) =
                            make_float2(acc[mf][nf][2], acc[mf][nf][3]);
                    }
                }
            }
            grid_barrier(nblk);

            // epilogue: sum ks partials + bias + TreeLSTM + bf16 cache
            for (int f = blockIdx.x * 256 + tid; f < M * HH; f += nblk * 256) {
                int j = f & 511, i = f >> 9;
                int item = g_items[start + i];
                int b = item >> 7, n = item & 127;
                int2 ch = g_ch[b * NN + n];
                float ga[5];
#pragma unroll
                for (int gg3 = 0; gg3 < 5; gg3++) {
                    float s = g_gates[(size_t)i * FIVE_H + gg3 * HH + j];
                    if (ks == 2)
                        s += g_gates[(size_t)(2048 + i) * FIVE_H + gg3 * HH + j];
                    ga[gg3] = s + rb[gg3 * HH + j];
                }
                float cl = csrc(b, ch.x)[j];
                float cr = csrc(b, ch.y)[j];
                float c = sigf(ga[1]) * cl + sigf(ga[2]) * cr + sigf(ga[0]) * tanhf(ga[4]);
                float h = sigf(ga[3]) * tanhf(c);
                int o = b * NN + n;
                g_node_h[o * HH + j] = h;
                g_node_c[o * HH + j] = c;
                store_nb(b, 128 + n, j, h);
            }
            grid_barrier(nblk);
        } else {
            // =============== FFMA2 split-K small paths (sv = 8) =============
            const int sv = 8;
            const int cpu = 4;
            const int units = 128;         // 16 col-tiles x 8 splits

            if (M > 32) {
                // ---- 128-node tile, thread = 4 nodes x 4 cols x 5 gates ----
                const int ng = tid >> 3, jg = tid & 7;
                for (int u = blockIdx.x; u < units; u += nblk) {
                    const int jt = u & 15;
                    const int split = u >> 4;
                    const int c0 = split * cpu, c1 = c0 + cpu;

                    if (tid < 128) {
                        int gi = start + tid;
                        bool valid = gi < start + M;
                        int item = g_items[valid ? gi : start];
                        int b = item >> 7, n = item & 127;
                        int2 ch = g_ch[b * NN + n];
                        C->hl[tid] = hsrc(b, ch.x);
                        C->hr[tid] = hsrc(b, ch.y);
                        C->idx[tid] = valid ? tid : -1;
                    }
                    __syncthreads();

                    ull acc[4][2][5];
#pragma unroll
                    for (int s = 0; s < 4; s++)
#pragma unroll
                        for (int p = 0; p < 2; p++)
#pragma unroll
                            for (int gg2 = 0; gg2 < 5; gg2++) acc[s][p][gg2] = 0ull;

                    for (int chk = c0; chk < c1; chk++) {
                        const int kc0 = chk * 32;
                        const bool left = kc0 < HH;
                        const int koff = left ? kc0 : (kc0 - HH);
#pragma unroll
                        for (int i = 0; i < 4; i++) {
                            int f = tid + i * 256;
                            int r = f >> 3, c4 = f & 7;
                            const float* bp2 = (left ? C->hl[r] : C->hr[r]) + koff;
                            float4 v = *(const float4*)(bp2 + c4 * 4);
                            Xs[(c4 * 4 + 0) * 129 + r] = v.x;
                            Xs[(c4 * 4 + 1) * 129 + r] = v.y;
                            Xs[(c4 * 4 + 2) * 129 + r] = v.z;
                            Xs[(c4 * 4 + 3) * 129 + r] = v.w;
                        }
#pragma unroll
                        for (int i = 0; i < 5; i++) {
                            int f4 = tid + i * 256;
                            int c4 = f4 & 7, gg2 = (f4 >> 3) % 5, k = f4 / 40;
                            *(float4*)&Ws[f4 * 4] =
                                *(const float4*)(W + (kc0 + k) * FIVE_H + gg2 * HH + jt * 32 + c4 * 4);
                        }
                        __syncthreads();
#pragma unroll 8
                        for (int k = 0; k < 32; k++) {
                            const float* xrow = Xs + k * 129 + ng * 4;
                            ull xp0 = pk2(xrow[0]);
                            ull xp1 = pk2(xrow[1]);
                            ull xp2 = pk2(xrow[2]);
                            ull xp3 = pk2(xrow[3]);
#pragma unroll
                            for (int gg2 = 0; gg2 < 5; gg2++) {
                                ulonglong2 w = *(const ulonglong2*)&Ws[(k * 5 + gg2) * 32 + jg * 4];
                                acc[0][0][gg2] = ffma2(xp0, w.x, acc[0][0][gg2]);
                                acc[0][1][gg2] = ffma2(xp0, w.y, acc[0][1][gg2]);
                                acc[1][0][gg2] = ffma2(xp1, w.x, acc[1][0][gg2]);
                                acc[1][1][gg2] = ffma2(xp1, w.y, acc[1][1][gg2]);
                                acc[2][0][gg2] = ffma2(xp2, w.x, acc[2][0][gg2]);
                                acc[2][1][gg2] = ffma2(xp2, w.y, acc[2][1][gg2]);
                                acc[3][0][gg2] = ffma2(xp3, w.x, acc[3][0][gg2]);
                                acc[3][1][gg2] = ffma2(xp3, w.y, acc[3][1][gg2]);
                            }
                        }
                        __syncthreads();
                    }

#pragma unroll
                    for (int s = 0; s < 4; s++) {
                        int r = ng * 4 + s;
                        int idx = C->idx[r];
                        if (idx < 0) continue;
#pragma unroll
                        for (int p = 0; p < 2; p++) {
                            int col = jt * 32 + jg * 4 + p * 2;
#pragma unroll
                            for (int gg2 = 0; gg2 < 5; gg2++) {
                                float2 v = upk(acc[s][p][gg2]);
                                int bi2 = (idx * FIVE_H + gg2 * HH + col) * PS + split;
                                g_part[bi2] = v.x;
                                g_part[bi2 + PS] = v.y;
                            }
                        }
                    }
                    __syncthreads();
                }
            } else {
                // ---- 32-node tile, thread = 1 node x 4 cols x 5 gates ------
                const int ngs = tid >> 3, qs = tid & 7;
                for (int u = blockIdx.x; u < units; u += nblk) {
                    const int jt = u & 15;
                    const int split = u >> 4;
                    const int c0 = split * cpu, c1 = c0 + cpu;

                    if (tid < 32) {
                        int gi = start + tid;
                        bool valid = gi < start + M;
                        int item = g_items[valid ? gi : start];
                        int b = item >> 7, n = item & 127;
                        int2 ch = g_ch[b * NN + n];
                        C->hl[tid] = hsrc(b, ch.x);
                        C->hr[tid] = hsrc(b, ch.y);
                        C->idx[tid] = valid ? tid : -1;
                    }
                    __syncthreads();

                    ull acc2[5][2];
#pragma unroll
                    for (int gg2 = 0; gg2 < 5; gg2++) { acc2[gg2][0] = 0ull; acc2[gg2][1] = 0ull; }

                    for (int chk = c0; chk < c1; chk++) {
                        const int kc0 = chk * 32;
                        const bool left = kc0 < HH;
                        const int koff = left ? kc0 : (kc0 - HH);
#pragma unroll
                        for (int i = 0; i < 4; i++) {
                            int f = tid + i * 256;
                            int node = f & 31, k = f >> 5;
                            Xs[k * 33 + node] = ((left ? C->hl[node] : C->hr[node]) + koff)[k];
                        }
#pragma unroll
                        for (int i = 0; i < 5; i++) {
                            int f4 = tid + i * 256;
                            int c4 = f4 & 7, gg2 = (f4 >> 3) % 5, k = f4 / 40;
                            *(float4*)&Ws[f4 * 4] =
                                *(const float4*)(W + (kc0 + k) * FIVE_H + gg2 * HH + jt * 32 + c4 * 4);
                        }
                        __syncthreads();
#pragma unroll 8
                        for (int k = 0; k < 32; k++) {
                            ull xp = pk2(Xs[k * 33 + ngs]);
#pragma unroll
                            for (int gg2 = 0; gg2 < 5; gg2++) {
                                ulonglong2 w = *(const ulonglong2*)&Ws[(k * 5 + gg2) * 32 + qs * 4];
                                acc2[gg2][0] = ffma2(xp, w.x, acc2[gg2][0]);
                                acc2[gg2][1] = ffma2(xp, w.y, acc2[gg2][1]);
                            }
                        }
                        __syncthreads();
                    }

                    {
                        int idx = C->idx[ngs];
                        if (idx >= 0) {
#pragma unroll
                            for (int gg2 = 0; gg2 < 5; gg2++)
#pragma unroll
                                for (int p = 0; p < 2; p++) {
                                    float2 v = upk(acc2[gg2][p]);
                                    int col = jt * 32 + qs * 4 + p * 2;
                                    int bi2 = (idx * FIVE_H + gg2 * HH + col) * PS + split;
                                    g_part[bi2] = v.x;
                                    g_part[bi2 + PS] = v.y;
                                }
                        }
                    }
                    __syncthreads();
                }
            }
            grid_barrier(nblk);

            // reduce partials (fixed order) + LSTM epilogue + bf16 cache
            for (int f = blockIdx.x * 256 + tid; f < M * HH; f += nblk * 256) {
                int j = f & 511, i = f >> 9;
                int item = g_items[start + i];
                int b = item >> 7, n = item & 127;
                int2 ch = g_ch[b * NN + n];
                float ga[5];
#pragma unroll
                for (int gg2 = 0; gg2 < 5; gg2++) {
                    int bb2 = (i * FIVE_H + gg2 * HH + j) * PS;
                    float s = 0.f;
#pragma unroll
                    for (int t = 0; t < sv; t++) s += g_part[bb2 + t];
                    ga[gg2] = s + rb[gg2 * HH + j];
                }
                float cl = csrc(b, ch.x)[j];
                float cr = csrc(b, ch.y)[j];
                float c = sigf(ga[1]) * cl + sigf(ga[2]) * cr + sigf(ga[0]) * tanhf(ga[4]);
                float h = sigf(ga[3]) * tanhf(c);
                int o = b * NN + n;
                g_node_h[o * HH + j] = h;
                g_node_c[o * HH + j] = c;
                store_nb(b, 128 + n, j, h);
            }
            grid_barrier(nblk);
        }
    }
}

// ------------------------- launch #5: final readout --------------------------
__global__ void final_kernel(float* __restrict__ out)
{
    int idx = blockIdx.x * blockDim.x + threadIdx.x;
    if (idx >= BB * HH) return;
    int b = idx >> 9;
    int j = idx & 511;
    int root = g_fin[b] - 128;
    out[idx] = g_node_h[(b * NN + root) * HH + j];
}

// ------------------------- launch -------------------------------------------
extern "C" void kernel_launch(void* const* d_in, const int* in_sizes, int n_in,
                              void* d_out, int out_size)
{
    const float* sentence    = (const float*)d_in[0];
    const int*   transitions = (const int*)  d_in[1];
    const float* word_W      = (const float*)d_in[2];
    const float* word_b      = (const float*)d_in[3];
    const float* bn_gamma    = (const float*)d_in[4];
    const float* bn_beta     = (const float*)d_in[5];
    const float* reduce_W    = (const float*)d_in[6];
    const float* reduce_b    = (const float*)d_in[7];
    float* out = (float*)d_out;

    int dev = 0, nsm = 148;
    cudaGetDevice(&dev);
    cudaDeviceGetAttribute(&nsm, cudaDevAttrMultiProcessorCount, dev);
    cudaFuncSetAttribute(scan_kernel, cudaFuncAttributeMaxDynamicSharedMemorySize, SMEM_SZ);

    // #1
    word_gemm<<<dim3(TWO_H / 64, NLE / 128), 256>>>(sentence, word_W, word_b);
    // #2 : bn_stats (1024) + wprep (10240) + meta (1)
    stats_wprep_meta<<<11265, 256>>>(reduce_W, transitions);
    // #3
    bn_apply_fin<<<4096, 256>>>(bn_gamma, bn_beta);
    // #4 : the kernel we want ncu to capture
    scan_kernel<<<nsm, 256, SMEM_SZ>>>(reduce_W, reduce_b, nsm);
    // #5
    final_kernel<<<(BB * HH + 255) / 256, 256>>>(out);
}

// round 17
// speedup vs baseline: 1.0490x; 1.0490x over previous
#include <cuda_runtime.h>
#include <cuda_bf16.h>
#include <math.h>

typedef unsigned long long ull;
typedef unsigned int uint;

// ---------------------------------------------------------------------------
// SPINN TreeLSTM: level-scheduled tree evaluation.
//   Big levels (M>128): mma.sync bf16x3, ldmatrix, 3-stage cp.async pipeline,
//                       contiguous per-level x conversion, split-K mid-size.
//   Mid levels (33..128): FFMA2 split-K, 128-node tile.
//   Tiny levels (<=32):   FFMA2 split-K, 32-node tile.
// scan_kernel stays launch #4 (ncu capture slot).
// R17: identical to R16 (container infra failure; code re-audited clean;
//      R14->R15 precedent shows identical resubmission succeeds).
// ---------------------------------------------------------------------------

#define BB 128
#define LL 128
#define EE 512
#define HH 512
#define TT 255
#define NN 127
#define TWO_H 1024
#define FIVE_H 2560
#define NLE (BB*LL)
#define PS 8

// dynamic smem: 3 chunk buffers of 40960B: [AH 10240 | AL 10240 | BH 10240 | BL 10240]
#define GBUF   40960
#define A_LO   10240
#define B_HI   20480
#define B_LO   30720
#define CTRL_OFF 122880
#define SMEM_SZ  131072

struct Ctrl {
    const float* hl[128];
    const float* hr[128];
    int  idx[128];
};

// ------------------------- scratch (static device memory) ------------------
__device__ float g_tmp[NLE * TWO_H];
__device__ float g_hbuf[BB * LL * HH];
__device__ float g_cbuf[BB * LL * HH];
__device__ float g_node_h[BB * NN * HH];
__device__ float g_node_c[BB * NN * HH];
__device__ float g_gates[8192 * FIVE_H];           // tensor-path gate preacts (+split slab)
__device__ float g_part[128 * FIVE_H * PS];        // small-path split-K partials
__device__ __nv_bfloat16 g_wb_hi[FIVE_H * TWO_H];  // W bf16 hi, [n][k]
__device__ __nv_bfloat16 g_wb_lo[FIVE_H * TWO_H];  // W bf16 lo, [n][k]
__device__ __nv_bfloat16 g_xa_hi[8192 * TWO_H];    // level x bf16 hi, [idx][k]
__device__ __nv_bfloat16 g_xa_lo[8192 * TWO_H];    // level x bf16 lo
__device__ float g_sum[TWO_H];
__device__ float g_sumsq[TWO_H];
__device__ int2  g_ch[BB * NN];
__device__ int   g_items[BB * NN];
__device__ int   g_lv_start[132];
__device__ int   g_maxlvl;
__device__ int   g_fin[BB];
__device__ int            g_bar_count;
__device__ volatile int   g_bar_gen;

__device__ __forceinline__ float sigf(float x) { return 1.0f / (1.0f + expf(-x)); }

__device__ __forceinline__ ull ffma2(ull x, ull w, ull a) {
    asm("fma.rn.f32x2 %0, %1, %2, %0;" : "+l"(a) : "l"(x), "l"(w));
    return a;
}
__device__ __forceinline__ ull pk2(float v) {
    ull r; asm("mov.b64 %0, {%1, %2};" : "=l"(r) : "f"(v), "f"(v)); return r;
}
__device__ __forceinline__ float2 upk(ull v) {
    float2 f; asm("mov.b64 {%0, %1}, %2;" : "=f"(f.x), "=f"(f.y) : "l"(v)); return f;
}
__device__ __forceinline__ uint s2u(const void* p) {
    uint a; asm("{ .reg .u64 t; cvta.to.shared.u64 t, %1; cvt.u32.u64 %0, t; }"
                : "=r"(a) : "l"(p));
    return a;
}

// cp.async 16B global->shared
__device__ __forceinline__ void cp16(uint dst, const void* src) {
    asm volatile("cp.async.cg.shared.global [%0], [%1], 16;" :: "r"(dst), "l"(src));
}
__device__ __forceinline__ void cp_commit() {
    asm volatile("cp.async.commit_group;" ::: "memory");
}
template <int N>
__device__ __forceinline__ void cp_wait() {
    asm volatile("cp.async.wait_group %0;" :: "n"(N) : "memory");
}

// mma.sync m16n8k16 row.col f32.bf16.bf16.f32
__device__ __forceinline__ void mma_bf16(float* c, uint a0, uint a1, uint a2, uint a3,
                                         uint b0, uint b1) {
    asm volatile("mma.sync.aligned.m16n8k16.row.col.f32.bf16.bf16.f32 "
                 "{%0,%1,%2,%3}, {%4,%5,%6,%7}, {%8,%9}, {%0,%1,%2,%3};"
                 : "+f"(c[0]), "+f"(c[1]), "+f"(c[2]), "+f"(c[3])
                 : "r"(a0), "r"(a1), "r"(a2), "r"(a3), "r"(b0), "r"(b1));
}

#define LDSM4(r0, r1, r2, r3, addr) asm volatile( \
    "ldmatrix.sync.aligned.m8n8.x4.shared.b16 {%0,%1,%2,%3}, [%4];" \
    : "=r"(r0), "=r"(r1), "=r"(r2), "=r"(r3) : "r"(addr))

__device__ __forceinline__ void cvt2(float a, float b, uint &hp, uint &lp) {
    __nv_bfloat16 ha = __float2bfloat16(a), hb = __float2bfloat16(b);
    float ra = a - __bfloat162float(ha);
    float rb2 = b - __bfloat162float(hb);
    __nv_bfloat16 la = __float2bfloat16(ra), lb = __float2bfloat16(rb2);
    hp = (uint)*(unsigned short*)&ha | ((uint)*(unsigned short*)&hb << 16);
    lp = (uint)*(unsigned short*)&la | ((uint)*(unsigned short*)&lb << 16);
}

__device__ __forceinline__ const float* hsrc(int b, int id) {
    return (id < 128) ? (g_hbuf + (b * LL + id) * HH)
                      : (g_node_h + (b * NN + (id - 128)) * HH);
}
__device__ __forceinline__ const float* csrc(int b, int id) {
    return (id < 128) ? (g_cbuf + (b * LL + id) * HH)
                      : (g_node_c + (b * NN + (id - 128)) * HH);
}

__device__ __forceinline__ void grid_barrier(int nblk) {
    __syncthreads();
    if (threadIdx.x == 0) {
        __threadfence();
        int gen = g_bar_gen;
        if (atomicAdd(&g_bar_count, 1) == nblk - 1) {
            g_bar_count = 0;
            __threadfence();
            g_bar_gen = gen + 1;
        } else {
            while (g_bar_gen == gen) { __nanosleep(32); }
        }
        __threadfence();
    }
    __syncthreads();
}

// ------------------- launch #1: word GEMM (f32x2) + stat zeroing ------------
__global__ __launch_bounds__(256) void word_gemm(
    const float* __restrict__ A, const float* __restrict__ Wm,
    const float* __restrict__ bias)
{
    __shared__ float As[32 * 129];
    __shared__ __align__(16) float Bs[32][64];
    const int tid = threadIdx.x;
    const int tx = tid & 15;
    const int ty = tid >> 4;
    const int rowBase = blockIdx.y * 128;
    const int colBase = blockIdx.x * 64;

    if (blockIdx.x == 0 && blockIdx.y == 0) {
        for (int i = tid; i < TWO_H; i += 256) { g_sum[i] = 0.f; g_sumsq[i] = 0.f; }
    }

    ull acc[8][2];
#pragma unroll
    for (int i = 0; i < 8; i++) { acc[i][0] = 0ull; acc[i][1] = 0ull; }

    for (int k0 = 0; k0 < EE; k0 += 32) {
#pragma unroll
        for (int i = 0; i < 4; i++) {
            int f = tid + i * 256;
            int r = f >> 3, c4 = f & 7;
            float4 v = *(const float4*)(A + (rowBase + r) * EE + k0 + c4 * 4);
            As[(c4 * 4 + 0) * 129 + r] = v.x;
            As[(c4 * 4 + 1) * 129 + r] = v.y;
            As[(c4 * 4 + 2) * 129 + r] = v.z;
            As[(c4 * 4 + 3) * 129 + r] = v.w;
        }
#pragma unroll
        for (int i = 0; i < 2; i++) {
            int f = tid + i * 256;
            int r = f >> 4, c4 = f & 15;
            *(float4*)&Bs[r][c4 * 4] =
                *(const float4*)(Wm + (k0 + r) * TWO_H + colBase + c4 * 4);
        }
        __syncthreads();
#pragma unroll 8
        for (int kk = 0; kk < 32; kk++) {
            const float* ar = As + kk * 129 + ty * 8;
            ulonglong2 w2 = *(const ulonglong2*)&Bs[kk][tx * 4];
#pragma unroll
            for (int i = 0; i < 8; i++) {
                ull xp = pk2(ar[i]);
                acc[i][0] = ffma2(xp, w2.x, acc[i][0]);
                acc[i][1] = ffma2(xp, w2.y, acc[i][1]);
            }
        }
        __syncthreads();
    }

    const int col = colBase + tx * 4;
    float2 b0 = *(const float2*)(bias + col);
    float2 b1 = *(const float2*)(bias + col + 2);
#pragma unroll
    for (int i = 0; i < 8; i++) {
        int row = rowBase + ty * 8 + i;
        float2 v0 = upk(acc[i][0]);
        float2 v1 = upk(acc[i][1]);
        v0.x += b0.x; v0.y += b0.y;
        v1.x += b1.x; v1.y += b1.y;
        *(float2*)&g_tmp[row * TWO_H + col] = v0;
        *(float2*)&g_tmp[row * TWO_H + col + 2] = v1;
    }
}

// ----- launch #2: fused bn_stats + wprep + meta tree build ------------------
__global__ __launch_bounds__(256) void stats_wprep_meta(
    const float* __restrict__ W, const int* __restrict__ trans)
{
    __shared__ int cnt[132];
    __shared__ int cur[132];
    __shared__ int smax;
    const int bx = blockIdx.x;
    const int tid = threadIdx.x;

    if (bx < 1024) {
        int ch = (bx & 3) * 256 + tid;
        int rowBase = (bx >> 2) * 64;
        float s = 0.f, q = 0.f;
#pragma unroll 4
        for (int r = 0; r < 64; r++) {
            float v = g_tmp[(rowBase + r) * TWO_H + ch];
            s += v; q += v * v;
        }
        atomicAdd(&g_sum[ch], s);
        atomicAdd(&g_sumsq[ch], q);
    } else if (bx < 11264) {
        int f = (bx - 1024) * 256 + tid;       // f = k*2560 + n
        if (f < TWO_H * FIVE_H) {
            int k = f / FIVE_H, n = f - k * FIVE_H;
            float w = W[f];
            __nv_bfloat16 hb = __float2bfloat16(w);
            float rest = w - __bfloat162float(hb);
            __nv_bfloat16 lb = __float2bfloat16(rest);
            g_wb_hi[n * TWO_H + k] = hb;
            g_wb_lo[n * TWO_H + k] = lb;
        }
    } else {
        int b = tid;
        for (int i = b; i < 132; i += 256) cnt[i] = 0;
        if (b == 0) smax = 0;
        __syncthreads();
        if (b < 128) {
            int sid[130];
            int slv[130];
            int nlv[NN];
            int ptr = 0, bp = 0, n = 0;
            for (int t = 0; t < TT; t++) {
                int act = trans[b * TT + t];
                if (act == 2) {
                    sid[ptr] = bp; slv[ptr] = 0; ptr++; bp++;
                } else if (act == 3) {
                    int lv = max(slv[ptr - 2], slv[ptr - 1]) + 1;
                    g_ch[b * NN + n] = make_int2(sid[ptr - 2], sid[ptr - 1]);
                    nlv[n] = lv;
                    sid[ptr - 2] = 128 + n; slv[ptr - 2] = lv;
                    ptr--; n++;
                }
            }
            g_fin[b] = sid[0];
            int mymax = 0;
            for (int i = 0; i < n; i++) {
                atomicAdd(&cnt[nlv[i]], 1);
                mymax = max(mymax, nlv[i]);
            }
            atomicMax(&smax, mymax);
            __syncthreads();
            if (b == 0) {
                int a = 0;
                for (int lv = 0; lv <= 130; lv++) {
                    cur[lv] = a;
                    g_lv_start[lv] = a;
                    a += cnt[lv];
                }
                g_lv_start[131] = a;
                g_maxlvl = smax;
            }
            __syncthreads();
            for (int i = 0; i < n; i++) {
                int idx = atomicAdd(&cur[nlv[i]], 1);
                g_items[idx] = (b << 7) | i;
            }
        } else {
            __syncthreads();
            __syncthreads();
        }
    }
}

// ------- launch #3: bn apply with inline finalize (16 rows / thread) --------
__global__ __launch_bounds__(256) void bn_apply_fin(
    const float* __restrict__ gamma, const float* __restrict__ beta)
{
    int id = blockIdx.x * 256 + threadIdx.x;       // < 1024*1024
    int ch = id & 1023;
    int rb2 = id >> 10;
    const float invN = 1.0f / (float)NLE;
    float mean = g_sum[ch] * invN;
    float var  = g_sumsq[ch] * invN - mean * mean;
    float sc   = gamma[ch] * rsqrtf(var + 1e-5f);
    float sh   = beta[ch] - mean * sc;
#pragma unroll 4
    for (int rr = 0; rr < 16; rr++) {
        int row = rb2 * 16 + rr;
        float v = g_tmp[row * TWO_H + ch] * sc + sh;
        if (ch < HH) g_hbuf[row * HH + ch] = v;
        else         g_cbuf[row * HH + (ch - HH)] = v;
    }
}

// ------------------- launch #4: persistent level-scan kernel ----------------
extern __shared__ char dsm_raw[];

__global__ __launch_bounds__(256) void scan_kernel(
    const float* __restrict__ W, const float* __restrict__ rb, int nblk)
{
    const int tid = threadIdx.x;
    const int lane = tid & 31;
    const int wid = tid >> 5;
    const int wm = wid >> 1;           // 0..3 : warp m-block (32 rows)
    const int wn = wid & 1;            // 0..1 : warp n-block (64 cols)
    const int g = lane >> 2;
    const int tig = lane & 3;

    char* base = dsm_raw;
    Ctrl* C = (Ctrl*)(base + CTRL_OFF);
    float* Xs = (float*)(base);            // small paths (aliases buffers)
    float* Ws = (float*)(base + 16896);
    const uint s0 = s2u(base);

    // ldmatrix per-thread address bases
    const int jmat = lane >> 3, jr = lane & 7;
    uint aBase[2], bBase[4];
    {
#pragma unroll
        for (int mf = 0; mf < 2; mf++)
            aBase[mf] = s0 + (uint)((wm * 32 + mf * 16 + (jmat & 1) * 8 + jr) * 80
                                    + (jmat >> 1) * 16);
#pragma unroll
        for (int p = 0; p < 4; p++)
            bBase[p] = s0 + B_HI + (uint)((wn * 64 + (2 * p + (jmat >> 1)) * 8 + jr) * 80
                                          + (jmat & 1) * 16);
    }

    const int r2 = tid >> 1, hf = tid & 1;       // cp.async staging coords
    const uint dst_d = (uint)(r2 * 80 + hf * 32);
    const int maxlvl = g_maxlvl;

    for (int lv = 1; lv <= maxlvl; lv++) {
        const int start = g_lv_start[lv];
        const int M = g_lv_start[lv + 1] - start;
        if (M <= 0) { grid_barrier(nblk); continue; }

        if (M > 128) {
            // ======== tensor path: per-level x -> bf16 hi/lo conversion =====
            int totalc = M * 64;                 // 16 elems per work item
            for (int u = blockIdx.x * 256 + tid; u < totalc; u += nblk * 256) {
                int i = u >> 6;
                int kq = (u & 63) << 4;
                int item = g_items[start + i];
                int b = item >> 7, n = item & 127;
                int2 ch = g_ch[b * NN + n];
                const float* src = (kq < HH) ? (hsrc(b, ch.x) + kq)
                                             : (hsrc(b, ch.y) + kq - HH);
                char* dh = (char*)(g_xa_hi + i * TWO_H + kq);
                char* dl = (char*)(g_xa_lo + i * TWO_H + kq);
#pragma unroll
                for (int q = 0; q < 4; q++) {
                    float4 v = *(const float4*)(src + q * 4);
                    uint h0, h1, l0, l1;
                    cvt2(v.x, v.y, h0, l0);
                    cvt2(v.z, v.w, h1, l1);
                    *(uint2*)(dh + q * 8) = make_uint2(h0, h1);
                    *(uint2*)(dl + q * 8) = make_uint2(l0, l1);
                }
            }
            grid_barrier(nblk);

            // ======== mma units: 128m x 128n tiles, cp.async 3-stage ========
            const int mtiles = (M + 127) >> 7;
            const int tiles0 = mtiles * 20;
            int ks = 1;
            if (tiles0 * 2 <= nblk) ks = 2;
            const int cpu2 = 32 / ks;
            const int units = tiles0 * ks;

            for (int u = blockIdx.x; u < units; u += nblk) {
                const int t2 = u % tiles0;
                const int sp = u / tiles0;
                const int mt = t2 / 20;
                const int nt = t2 - mt * 20;
                const int c0 = sp * cpu2, c1 = c0 + cpu2;

                const __nv_bfloat16* sa_h0 = g_xa_hi + (size_t)(mt * 128 + r2) * TWO_H;
                const __nv_bfloat16* sa_l0 = g_xa_lo + (size_t)(mt * 128 + r2) * TWO_H;
                const __nv_bfloat16* sb_h0 = g_wb_hi + (size_t)(nt * 128 + r2) * TWO_H;
                const __nv_bfloat16* sb_l0 = g_wb_lo + (size_t)(nt * 128 + r2) * TWO_H;

                // issue first 3 stages
#pragma unroll
                for (int st = 0; st < 3; st++) {
                    int chk = c0 + st;
                    uint db = s0 + (uint)st * GBUF + dst_d;
                    int ko = chk * 32 + hf * 16;
                    cp16(db,                 sa_h0 + ko);
                    cp16(db + 16,            sa_h0 + ko + 8);
                    cp16(db + A_LO,          sa_l0 + ko);
                    cp16(db + A_LO + 16,     sa_l0 + ko + 8);
                    cp16(db + B_HI,          sb_h0 + ko);
                    cp16(db + B_HI + 16,     sb_h0 + ko + 8);
                    cp16(db + B_LO,          sb_l0 + ko);
                    cp16(db + B_LO + 16,     sb_l0 + ko + 8);
                    cp_commit();
                }

                float acc[2][8][4];
#pragma unroll
                for (int mf = 0; mf < 2; mf++)
#pragma unroll
                    for (int nf = 0; nf < 8; nf++)
#pragma unroll
                        for (int q = 0; q < 4; q++) acc[mf][nf][q] = 0.f;

                int bufi = 0;
                for (int chk = c0; chk < c1; chk++) {
                    if (chk + 2 < c1)      cp_wait<2>();
                    else if (chk + 1 < c1) cp_wait<1>();
                    else                   cp_wait<0>();
                    __syncthreads();

                    const uint bufo = (uint)bufi * GBUF;
#pragma unroll
                    for (int half = 0; half < 2; half++) {
                        const uint kb = bufo + (uint)half * 32;
                        uint bh[8][2], bl[8][2];
#pragma unroll
                        for (int p = 0; p < 4; p++) {
                            LDSM4(bh[2 * p][0], bh[2 * p][1],
                                  bh[2 * p + 1][0], bh[2 * p + 1][1], bBase[p] + kb);
                            LDSM4(bl[2 * p][0], bl[2 * p][1],
                                  bl[2 * p + 1][0], bl[2 * p + 1][1],
                                  bBase[p] + kb + (B_LO - B_HI));
                        }
#pragma unroll
                        for (int mf = 0; mf < 2; mf++) {
                            uint a0, a1, a2, a3, l0, l1, l2, l3;
                            LDSM4(a0, a1, a2, a3, aBase[mf] + kb);
                            LDSM4(l0, l1, l2, l3, aBase[mf] + kb + A_LO);
#pragma unroll
                            for (int nf = 0; nf < 8; nf++) {
                                mma_bf16(acc[mf][nf], a0, a1, a2, a3, bh[nf][0], bh[nf][1]);
                                mma_bf16(acc[mf][nf], l0, l1, l2, l3, bh[nf][0], bh[nf][1]);
                                mma_bf16(acc[mf][nf], a0, a1, a2, a3, bl[nf][0], bl[nf][1]);
                            }
                        }
                    }
                    __syncthreads();

                    if (chk + 3 < c1) {
                        uint db = s0 + (uint)bufi * GBUF + dst_d;
                        int ko = (chk + 3) * 32 + hf * 16;
                        cp16(db,                 sa_h0 + ko);
                        cp16(db + 16,            sa_h0 + ko + 8);
                        cp16(db + A_LO,          sa_l0 + ko);
                        cp16(db + A_LO + 16,     sa_l0 + ko + 8);
                        cp16(db + B_HI,          sb_h0 + ko);
                        cp16(db + B_HI + 16,     sb_h0 + ko + 8);
                        cp16(db + B_LO,          sb_l0 + ko);
                        cp16(db + B_LO + 16,     sb_l0 + ko + 8);
                        cp_commit();
                    }
                    bufi = (bufi == 2) ? 0 : bufi + 1;
                }

                // write accumulators (split slab sp*2048 rows)
#pragma unroll
                for (int mf = 0; mf < 2; mf++) {
                    int row = wm * 32 + mf * 16 + g;
                    int gi = sp * 2048 + mt * 128 + row;
                    float* dst0 = g_gates + (size_t)gi * FIVE_H;
#pragma unroll
                    for (int nf = 0; nf < 8; nf++) {
                        int col = nt * 128 + wn * 64 + nf * 8 + 2 * tig;
                        *(float2*)(dst0 + col) =
                            make_float2(acc[mf][nf][0], acc[mf][nf][1]);
                        *(float2*)(dst0 + 8 * FIVE_H + col) =
                            make_float2(acc[mf][nf][2], acc[mf][nf][3]);
                    }
                }
            }
            grid_barrier(nblk);

            // epilogue: sum ks partials + bias + TreeLSTM
            for (int f = blockIdx.x * 256 + tid; f < M * HH; f += nblk * 256) {
                int j = f & 511, i = f >> 9;
                int item = g_items[start + i];
                int b = item >> 7, n = item & 127;
                int2 ch = g_ch[b * NN + n];
                float ga[5];
#pragma unroll
                for (int gg3 = 0; gg3 < 5; gg3++) {
                    float s = g_gates[(size_t)i * FIVE_H + gg3 * HH + j];
                    if (ks == 2)
                        s += g_gates[(size_t)(2048 + i) * FIVE_H + gg3 * HH + j];
                    ga[gg3] = s + rb[gg3 * HH + j];
                }
                float cl = csrc(b, ch.x)[j];
                float cr = csrc(b, ch.y)[j];
                float c = sigf(ga[1]) * cl + sigf(ga[2]) * cr + sigf(ga[0]) * tanhf(ga[4]);
                float h = sigf(ga[3]) * tanhf(c);
                int o = b * NN + n;
                g_node_h[o * HH + j] = h;
                g_node_c[o * HH + j] = c;
            }
            grid_barrier(nblk);
        } else {
            // =============== FFMA2 split-K small paths (sv = 8) =============
            const int sv = 8;
            const int cpu = 4;
            const int units = 128;         // 16 col-tiles x 8 splits

            if (M > 32) {
                // ---- 128-node tile, thread = 4 nodes x 4 cols x 5 gates ----
                const int ng = tid >> 3, jg = tid & 7;
                for (int u = blockIdx.x; u < units; u += nblk) {
                    const int jt = u & 15;
                    const int split = u >> 4;
                    const int c0 = split * cpu, c1 = c0 + cpu;

                    if (tid < 128) {
                        int gi = start + tid;
                        bool valid = gi < start + M;
                        int item = g_items[valid ? gi : start];
                        int b = item >> 7, n = item & 127;
                        int2 ch = g_ch[b * NN + n];
                        C->hl[tid] = hsrc(b, ch.x);
                        C->hr[tid] = hsrc(b, ch.y);
                        C->idx[tid] = valid ? tid : -1;
                    }
                    __syncthreads();

                    ull acc[4][2][5];
#pragma unroll
                    for (int s = 0; s < 4; s++)
#pragma unroll
                        for (int p = 0; p < 2; p++)
#pragma unroll
                            for (int gg2 = 0; gg2 < 5; gg2++) acc[s][p][gg2] = 0ull;

                    for (int chk = c0; chk < c1; chk++) {
                        const int kc0 = chk * 32;
                        const bool left = kc0 < HH;
                        const int koff = left ? kc0 : (kc0 - HH);
#pragma unroll
                        for (int i = 0; i < 4; i++) {
                            int f = tid + i * 256;
                            int r = f >> 3, c4 = f & 7;
                            const float* bp2 = (left ? C->hl[r] : C->hr[r]) + koff;
                            float4 v = *(const float4*)(bp2 + c4 * 4);
                            Xs[(c4 * 4 + 0) * 129 + r] = v.x;
                            Xs[(c4 * 4 + 1) * 129 + r] = v.y;
                            Xs[(c4 * 4 + 2) * 129 + r] = v.z;
                            Xs[(c4 * 4 + 3) * 129 + r] = v.w;
                        }
#pragma unroll
                        for (int i = 0; i < 5; i++) {
                            int f4 = tid + i * 256;
                            int c4 = f4 & 7, gg2 = (f4 >> 3) % 5, k = f4 / 40;
                            *(float4*)&Ws[f4 * 4] =
                                *(const float4*)(W + (kc0 + k) * FIVE_H + gg2 * HH + jt * 32 + c4 * 4);
                        }
                        __syncthreads();
#pragma unroll 8
                        for (int k = 0; k < 32; k++) {
                            const float* xrow = Xs + k * 129 + ng * 4;
                            ull xp0 = pk2(xrow[0]);
                            ull xp1 = pk2(xrow[1]);
                            ull xp2 = pk2(xrow[2]);
                            ull xp3 = pk2(xrow[3]);
#pragma unroll
                            for (int gg2 = 0; gg2 < 5; gg2++) {
                                ulonglong2 w = *(const ulonglong2*)&Ws[(k * 5 + gg2) * 32 + jg * 4];
                                acc[0][0][gg2] = ffma2(xp0, w.x, acc[0][0][gg2]);
                                acc[0][1][gg2] = ffma2(xp0, w.y, acc[0][1][gg2]);
                                acc[1][0][gg2] = ffma2(xp1, w.x, acc[1][0][gg2]);
                                acc[1][1][gg2] = ffma2(xp1, w.y, acc[1][1][gg2]);
                                acc[2][0][gg2] = ffma2(xp2, w.x, acc[2][0][gg2]);
                                acc[2][1][gg2] = ffma2(xp2, w.y, acc[2][1][gg2]);
                                acc[3][0][gg2] = ffma2(xp3, w.x, acc[3][0][gg2]);
                                acc[3][1][gg2] = ffma2(xp3, w.y, acc[3][1][gg2]);
                            }
                        }
                        __syncthreads();
                    }

#pragma unroll
                    for (int s = 0; s < 4; s++) {
                        int r = ng * 4 + s;
                        int idx = C->idx[r];
                        if (idx < 0) continue;
#pragma unroll
                        for (int p = 0; p < 2; p++) {
                            int col = jt * 32 + jg * 4 + p * 2;
#pragma unroll
                            for (int gg2 = 0; gg2 < 5; gg2++) {
                                float2 v = upk(acc[s][p][gg2]);
                                int bi2 = (idx * FIVE_H + gg2 * HH + col) * PS + split;
                                g_part[bi2] = v.x;
                                g_part[bi2 + PS] = v.y;
                            }
                        }
                    }
                    __syncthreads();
                }
            } else {
                // ---- 32-node tile, thread = 1 node x 4 cols x 5 gates ------
                const int ngs = tid >> 3, qs = tid & 7;
                for (int u = blockIdx.x; u < units; u += nblk) {
                    const int jt = u & 15;
                    const int split = u >> 4;
                    const int c0 = split * cpu, c1 = c0 + cpu;

                    if (tid < 32) {
                        int gi = start + tid;
                        bool valid = gi < start + M;
                        int item = g_items[valid ? gi : start];
                        int b = item >> 7, n = item & 127;
                        int2 ch = g_ch[b * NN + n];
                        C->hl[tid] = hsrc(b, ch.x);
                        C->hr[tid] = hsrc(b, ch.y);
                        C->idx[tid] = valid ? tid : -1;
                    }
                    __syncthreads();

                    ull acc2[5][2];
#pragma unroll
                    for (int gg2 = 0; gg2 < 5; gg2++) { acc2[gg2][0] = 0ull; acc2[gg2][1] = 0ull; }

                    for (int chk = c0; chk < c1; chk++) {
                        const int kc0 = chk * 32;
                        const bool left = kc0 < HH;
                        const int koff = left ? kc0 : (kc0 - HH);
#pragma unroll
                        for (int i = 0; i < 4; i++) {
                            int f = tid + i * 256;
                            int node = f & 31, k = f >> 5;
                            Xs[k * 33 + node] = ((left ? C->hl[node] : C->hr[node]) + koff)[k];
                        }
#pragma unroll
                        for (int i = 0; i < 5; i++) {
                            int f4 = tid + i * 256;
                            int c4 = f4 & 7, gg2 = (f4 >> 3) % 5, k = f4 / 40;
                            *(float4*)&Ws[f4 * 4] =
                                *(const float4*)(W + (kc0 + k) * FIVE_H + gg2 * HH + jt * 32 + c4 * 4);
                        }
                        __syncthreads();
#pragma unroll 8
                        for (int k = 0; k < 32; k++) {
                            ull xp = pk2(Xs[k * 33 + ngs]);
#pragma unroll
                            for (int gg2 = 0; gg2 < 5; gg2++) {
                                ulonglong2 w = *(const ulonglong2*)&Ws[(k * 5 + gg2) * 32 + qs * 4];
                                acc2[gg2][0] = ffma2(xp, w.x, acc2[gg2][0]);
                                acc2[gg2][1] = ffma2(xp, w.y, acc2[gg2][1]);
                            }
                        }
                        __syncthreads();
                    }

                    {
                        int idx = C->idx[ngs];
                        if (idx >= 0) {
#pragma unroll
                            for (int gg2 = 0; gg2 < 5; gg2++)
#pragma unroll
                                for (int p = 0; p < 2; p++) {
                                    float2 v = upk(acc2[gg2][p]);
                                    int col = jt * 32 + qs * 4 + p * 2;
                                    int bi2 = (idx * FIVE_H + gg2 * HH + col) * PS + split;
                                    g_part[bi2] = v.x;
                                    g_part[bi2 + PS] = v.y;
                                }
                        }
                    }
                    __syncthreads();
                }
            }
            grid_barrier(nblk);

            // reduce partials (fixed order) + LSTM epilogue
            for (int f = blockIdx.x * 256 + tid; f < M * HH; f += nblk * 256) {
                int j = f & 511, i = f >> 9;
                int item = g_items[start + i];
                int b = item >> 7, n = item & 127;
                int2 ch = g_ch[b * NN + n];
                float ga[5];
#pragma unroll
                for (int gg2 = 0; gg2 < 5; gg2++) {
                    int bb2 = (i * FIVE_H + gg2 * HH + j) * PS;
                    float s = 0.f;
#pragma unroll
                    for (int t = 0; t < sv; t++) s += g_part[bb2 + t];
                    ga[gg2] = s + rb[gg2 * HH + j];
                }
                float cl = csrc(b, ch.x)[j];
                float cr = csrc(b, ch.y)[j];
                float c = sigf(ga[1]) * cl + sigf(ga[2]) * cr + sigf(ga[0]) * tanhf(ga[4]);
                float h = sigf(ga[3]) * tanhf(c);
                int o = b * NN + n;
                g_node_h[o * HH + j] = h;
                g_node_c[o * HH + j] = c;
            }
            grid_barrier(nblk);
        }
    }
}

// ------------------------- launch #5: final readout --------------------------
__global__ void final_kernel(float* __restrict__ out)
{
    int idx = blockIdx.x * blockDim.x + threadIdx.x;
    if (idx >= BB * HH) return;
    int b = idx >> 9;
    int j = idx & 511;
    int root = g_fin[b] - 128;
    out[idx] = g_node_h[(b * NN + root) * HH + j];
}

// ------------------------- launch -------------------------------------------
extern "C" void kernel_launch(void* const* d_in, const int* in_sizes, int n_in,
                              void* d_out, int out_size)
{
    const float* sentence    = (const float*)d_in[0];
    const int*   transitions = (const int*)  d_in[1];
    const float* word_W      = (const float*)d_in[2];
    const float* word_b      = (const float*)d_in[3];
    const float* bn_gamma    = (const float*)d_in[4];
    const float* bn_beta     = (const float*)d_in[5];
    const float* reduce_W    = (const float*)d_in[6];
    const float* reduce_b    = (const float*)d_in[7];
    float* out = (float*)d_out;

    int dev = 0, nsm = 148;
    cudaGetDevice(&dev);
    cudaDeviceGetAttribute(&nsm, cudaDevAttrMultiProcessorCount, dev);
    cudaFuncSetAttribute(scan_kernel, cudaFuncAttributeMaxDynamicSharedMemorySize, SMEM_SZ);

    // #1
    word_gemm<<<dim3(TWO_H / 64, NLE / 128), 256>>>(sentence, word_W, word_b);
    // #2 : bn_stats (1024) + wprep (10240) + meta (1)
    stats_wprep_meta<<<11265, 256>>>(reduce_W, transitions);
    // #3
    bn_apply_fin<<<4096, 256>>>(bn_gamma, bn_beta);
    // #4 : the kernel we want ncu to capture
    scan_kernel<<<nsm, 256, SMEM_SZ>>>(reduce_W, reduce_b, nsm);
    // #5
    final_kernel<<<(BB * HH + 255) / 256, 256>>>(out);
}